// round 14
// baseline (speedup 1.0000x reference)
#include <cuda_runtime.h>
#include <stdint.h>

#define BATCH  4096
#define IN_F   2048
#define OUT_F  4096
#define HT_SIZE 16384
#define HT_MASK (HT_SIZE - 1)
#define KCAP   8

// Scratch (allocation-free: __device__ globals; zero-init at load, and
// returned to zero by kernel 2 every run -> graph replays are deterministic).
__device__ uint64_t g_ht[HT_SIZE];            // [63:32] sig32, [31] marker, [30] type, [29:0] row id
__device__ uint32_t g_cnt[BATCH];             // matches found for batch row b
__device__ uint32_t g_olist[BATCH][KCAP];     // the matching o's (overflow -> full rescan)

__device__ __forceinline__ bool path_bit(float wv, float rv)
{
    // BinGen/BSGen: prob=(w+1)*0.5; source=round(prob*256); bit = source > rng.
    // rintf = round-half-to-even, matching jnp.round exactly.
    return rintf((wv + 1.0f) * 0.5f * 256.0f) > rv;
}

// Exact pair verification straight from the const inputs (no ordering needed
// vs other blocks' scratch writes). Early-exits after ~2 elements for random
// non-matching rows.
__device__ bool verify_pair(const float* __restrict__ x,
                            const float* __restrict__ w,
                            float rv, int b, int o)
{
    const float* xr = x + (size_t)b * IN_F;
    const float* wr = w + (size_t)o * IN_F;
    for (int k = 0; k < IN_F; ++k)
        if ((__ldg(xr + k) > 0.5f) != path_bit(__ldg(wr + k), rv)) return false;
    return true;
}

// -----------------------------------------------------------------------------
// Kernel 1: pure 64 MB read stream. 1024 blocks x 256 threads, one warp/row
// (first 4096 warps = x rows, rest = path rows).
//   * Thread-local nibble pack: lane packs elements {it*128 + lane*4 + j} into
//     bit (4*it+j) of its own u64 — a fixed permutation of element order,
//     IDENTICAL for x and path rows, so sig equality is implied by row
//     equality. No ballots -> loads pipeline freely.
//   * sig32 = fold(xor-reduce(lane-salted mix)), then lane 0 inserts into the
//     global hash table. Insert-time detection: any equal-sig opposite-type
//     entry in the probe chain is a candidate pair (the LATER inserter of any
//     matching pair always walks past the earlier one), verified exactly from
//     the inputs and recorded in g_cnt/g_olist.
// -----------------------------------------------------------------------------
__global__ __launch_bounds__(256) void fsu_sig_kernel(
    const float* __restrict__ x,
    const float* __restrict__ w,
    const float* __restrict__ rng)
{
    const int gwarp = (blockIdx.x * blockDim.x + threadIdx.x) >> 5;
    const int lane  = threadIdx.x & 31;
    const bool isX  = gwarp < BATCH;
    const int row   = isX ? gwarp : (gwarp - BATCH);

    const float rv = __ldg(rng);
    const float4* src = reinterpret_cast<const float4*>(
        (isX ? (x + (size_t)row * IN_F) : (w + (size_t)row * IN_F)));

    uint32_t lo = 0, hi = 0;

    #pragma unroll
    for (int it = 0; it < 16; ++it) {
        const float4 v = __ldg(src + it * 32 + lane);
        uint32_t b0, b1, b2, b3;
        if (isX) {
            b0 = (v.x > 0.5f); b1 = (v.y > 0.5f);
            b2 = (v.z > 0.5f); b3 = (v.w > 0.5f);
        } else {
            b0 = path_bit(v.x, rv); b1 = path_bit(v.y, rv);
            b2 = path_bit(v.z, rv); b3 = path_bit(v.w, rv);
        }
        const uint32_t nib = b0 | (b1 << 1) | (b2 << 2) | (b3 << 3);
        if (it < 8) lo |= nib << (4 * it);
        else        hi |= nib << (4 * (it - 8));
    }

    // lane-salted mix, XOR butterfly reduce -> row signature (deterministic
    // function of the row's bits; equal rows => equal sig)
    uint64_t s = ((uint64_t)lo | ((uint64_t)hi << 32))
               + 0x9E3779B97F4A7C15ull * (uint64_t)(lane + 1);
    s ^= s >> 33; s *= 0xff51afd7ed558ccdULL; s ^= s >> 29;
    #pragma unroll
    for (int off = 16; off > 0; off >>= 1)
        s ^= __shfl_xor_sync(0xFFFFFFFFu, (unsigned long long)s, off);

    const uint32_t sig32 = (uint32_t)(s ^ (s >> 32));

    if (lane == 0) {
        const uint64_t entry = ((uint64_t)sig32 << 32) | 0x80000000u
                             | ((uint64_t)(isX ? 1 : 0) << 30) | (uint32_t)row;
        uint32_t h = (sig32 * 2654435761u) >> 18;      // 14-bit home slot
        while (true) {
            const unsigned long long prev =
                atomicCAS((unsigned long long*)&g_ht[h], 0ull,
                          (unsigned long long)entry);
            if (prev == 0ull) break;                   // claimed a slot
            // occupied (or lost the race): examine the occupant
            if ((uint32_t)(prev >> 32) == sig32 &&
                (((prev >> 30) & 1ull) != (uint64_t)(isX ? 1 : 0))) {
                const int oid = (int)(prev & 0x3FFFFFFFull);
                const int b = isX ? row : oid;
                const int o = isX ? oid : row;
                if (verify_pair(x, w, rv, b, o)) {
                    const uint32_t idx = atomicAdd(&g_cnt[b], 1u);
                    if (idx < KCAP) g_olist[b][idx] = (uint32_t)o;
                }
            }
            h = (h + 1) & HT_MASK;
        }
    }
}

// -----------------------------------------------------------------------------
// Kernel 2: pure 64 MB write stream. 512 blocks x 256 threads; block owns 8
// output rows: zero-fills them (32 float4/thread), then applies any recorded
// matches for ITS rows (no cross-block store races; launch boundary ordered
// the list writes). Also clears its 32 hash-table slots and resets its rows'
// counters so the next graph replay starts clean. Typical path: counters all
// zero -> just the store stream + 1 tiny L2 read.
// -----------------------------------------------------------------------------
__global__ __launch_bounds__(256) void fsu_out_kernel(
    const float* __restrict__ x,
    const float* __restrict__ w,
    const float* __restrict__ rng,
    float* __restrict__ out)
{
    const int tid   = threadIdx.x;
    const int bbase = blockIdx.x * 8;

    // zero-fill this block's 8 rows
    {
        float4* outv = reinterpret_cast<float4*>(out) + (size_t)bbase * (OUT_F / 4);
        const float4 z = make_float4(0.0f, 0.0f, 0.0f, 0.0f);
        #pragma unroll
        for (int k = 0; k < 32; ++k)
            outv[k * 256 + tid] = z;
    }

    // cleanup: clear this block's hash-table slice (512 blocks x 32 = 16384)
    if (tid < 32) g_ht[blockIdx.x * 32 + tid] = 0ull;

    // match check for this block's rows
    __shared__ uint32_t s_cnt[8];
    if (tid < 8) s_cnt[tid] = g_cnt[bbase + tid];
    __syncthreads();

    uint32_t any = 0;
    #pragma unroll
    for (int r = 0; r < 8; ++r) any |= s_cnt[r];
    if (any == 0) return;                              // typical path

    // rare path: apply matches after this block's own zeros (__syncthreads
    // above established intra-block ordering)
    const float rv = __ldg(rng);
    for (int r = 0; r < 8; ++r) {
        const uint32_t n = s_cnt[r];
        if (n == 0) continue;
        const int b = bbase + r;
        if (n <= KCAP) {
            if (tid < (int)n)
                out[(size_t)b * OUT_F + g_olist[b][tid]] = 1.0f;
        } else {
            // overflow (needs >8 identical rows — effectively impossible, but
            // stays exact): full rescan of row b against all path rows
            for (int o = tid; o < OUT_F; o += 256)
                if (verify_pair(x, w, rv, b, o))
                    out[(size_t)b * OUT_F + o] = 1.0f;
        }
        if (tid == 0) g_cnt[b] = 0;                    // reset for next replay
    }
}

extern "C" void kernel_launch(void* const* d_in, const int* in_sizes, int n_in,
                              void* d_out, int out_size)
{
    const float* x   = (const float*)d_in[0];
    const float* w   = (const float*)d_in[1];
    const float* rng = (const float*)d_in[2];
    float* out = (float*)d_out;

    fsu_sig_kernel<<<(BATCH + OUT_F) / 8, 256>>>(x, w, rng);   // 1024 blocks, 64 MB read
    fsu_out_kernel<<<BATCH / 8, 256>>>(x, w, rng, out);        // 512 blocks, 64 MB write
}

// round 15
// speedup vs baseline: 1.1635x; 1.1635x over previous
#include <cuda_runtime.h>
#include <stdint.h>

#define BATCH 4096
#define IN_F  2048
#define OUT_F 4096
#define WORDS (IN_F / 64)     // 32 u64 per row
#define MROWS 32              // batch rows per match block

// Scratch (allocation-free: __device__ globals)
__device__ uint64_t g_xbits[(size_t)BATCH * WORDS];
__device__ uint64_t g_pbits[(size_t)OUT_F * WORDS];
__device__ uint32_t g_xsig[BATCH];
__device__ uint32_t g_psig[OUT_F];

// -----------------------------------------------------------------------------
// Kernel 1: fused pack + zero-fill (HBM-bound: 64 MB read + 64 MB write).
//   1024 blocks x 256 threads. Each block packs 8 rows (one warp per row)
//   AND zero-fills a 4096-float4 slice of the output.
//   Pack: float4 loads (.cs — read-once), 4 ballots/iter. Bit order within
//   packed words is a fixed permutation of element order, identical for x and
//   path rows, so packed-row equality <=> original-bit-row equality (exact).
//   Signature folded to 32 bits; every sig hit is exactly verified downstream.
// -----------------------------------------------------------------------------
__global__ __launch_bounds__(256) void fsu_pack_zero_kernel(
    const float* __restrict__ x,
    const float* __restrict__ w,
    const float* __restrict__ rng,
    float4* __restrict__ outv)
{
    // ---- zero-fill slice (pure store stream, overlaps with pack loads) ----
    {
        const float4 z = make_float4(0.0f, 0.0f, 0.0f, 0.0f);
        const int base = blockIdx.x * 4096;          // 4M float4 / 1024 blocks
        #pragma unroll
        for (int k = 0; k < 16; ++k)
            __stcs(&outv[base + k * 256 + threadIdx.x], z);
    }

    // ---- pack 8 rows (one warp per row) ----
    const int gwarp = (blockIdx.x * blockDim.x + threadIdx.x) >> 5;
    const int lane  = threadIdx.x & 31;
    const bool isX  = gwarp < BATCH;
    const int row   = isX ? gwarp : (gwarp - BATCH);

    const float rv = __ldg(rng);
    const float4* src = reinterpret_cast<const float4*>(
        (isX ? (x + (size_t)row * IN_F) : (w + (size_t)row * IN_F)));

    uint64_t sig = 0;
    uint64_t myword = 0;

    #pragma unroll
    for (int it = 0; it < IN_F / 128; ++it) {        // 16 iterations
        const float4 v = __ldcs(src + it * 32 + lane);
        bool b0, b1, b2, b3;
        if (isX) {
            b0 = (v.x > 0.5f); b1 = (v.y > 0.5f);
            b2 = (v.z > 0.5f); b3 = (v.w > 0.5f);
        } else {
            // BinGen/BSGen: prob=(w+1)*0.5; source=round(prob*256); bit = source > rng
            b0 = (rintf((v.x + 1.0f) * 0.5f * 256.0f) > rv);
            b1 = (rintf((v.y + 1.0f) * 0.5f * 256.0f) > rv);
            b2 = (rintf((v.z + 1.0f) * 0.5f * 256.0f) > rv);
            b3 = (rintf((v.w + 1.0f) * 0.5f * 256.0f) > rv);
        }
        const uint32_t m0 = __ballot_sync(0xFFFFFFFFu, b0);
        const uint32_t m1 = __ballot_sync(0xFFFFFFFFu, b1);
        const uint32_t m2 = __ballot_sync(0xFFFFFFFFu, b2);
        const uint32_t m3 = __ballot_sync(0xFFFFFFFFu, b3);
        const uint64_t wa = (uint64_t)m0 | ((uint64_t)m1 << 32);
        const uint64_t wb = (uint64_t)m2 | ((uint64_t)m3 << 32);
        if (lane == 2 * it)     myword = wa;
        if (lane == 2 * it + 1) myword = wb;
        sig = sig * 0x9E3779B97F4A7C15ull + wa;
        sig = sig * 0x9E3779B97F4A7C15ull + wb;
    }

    // fold to 32 bits (equal rows -> equal sig32; verification is exact anyway)
    sig *= 0xff51afd7ed558ccdULL;
    const uint32_t sig32 = (uint32_t)(sig ^ (sig >> 32));

    if (isX) {
        g_xbits[(size_t)row * WORDS + lane] = myword;
        if (lane == 0) g_xsig[row] = sig32;
    } else {
        g_pbits[(size_t)row * WORDS + lane] = myword;
        if (lane == 0) g_psig[row] = sig32;
    }
}

// Exact verification: full 2048-bit compare. Equal sigs alone is never
// trusted — collisions cannot produce wrong output.
__device__ __noinline__ bool fsu_full_cmp(int b, int o)
{
    const uint64_t* xb = &g_xbits[(size_t)b * WORDS];
    const uint64_t* pb = &g_pbits[(size_t)o * WORDS];
    #pragma unroll 8
    for (int k = 0; k < WORDS; ++k)
        if (__ldg(xb + k) != __ldg(pb + k)) return false;
    return true;
}

// -----------------------------------------------------------------------------
// Kernel 2: bloom-filtered sig match. 128 blocks x 1024 threads. Block owns
// MROWS=32 batch rows: builds a 4096-bit smem bloom bitmap of their sig32s,
// then each thread tests 4 psigs against the bitmap (1 LDS + bit test each,
// ~0.8% hit rate) instead of 32 compares each. Bitmap hits fall through to
// the exact 32-way compare + full 2048-bit verification -> unconditionally
// correct. out[] already zeroed by kernel 1 (stream order).
// -----------------------------------------------------------------------------
__global__ __launch_bounds__(1024) void fsu_match_kernel(float* __restrict__ out)
{
    __shared__ uint32_t s_bloom[128];                // 4096 bits
    __shared__ uint32_t s_xsig[MROWS];

    const int tid   = threadIdx.x;
    const int bbase = blockIdx.x * MROWS;

    if (tid < 128) s_bloom[tid] = 0;
    __syncthreads();
    if (tid < MROWS) {
        const uint32_t sx = __ldg(&g_xsig[bbase + tid]);
        s_xsig[tid] = sx;
        atomicOr(&s_bloom[(sx >> 5) & 127], 1u << (sx & 31));
    }
    __syncthreads();

    #pragma unroll
    for (int k = 0; k < OUT_F / 1024; ++k) {         // 4 psigs per thread
        const int o = k * 1024 + tid;
        const uint32_t ps = __ldg(&g_psig[o]);
        if ((s_bloom[(ps >> 5) & 127] >> (ps & 31)) & 1u) {
            // rare: resolve which row(s) actually match this sig
            #pragma unroll 4
            for (int r = 0; r < MROWS; ++r) {
                if (ps == s_xsig[r]) {
                    const int b = bbase + r;
                    if (fsu_full_cmp(b, o))
                        out[(size_t)b * OUT_F + o] = 1.0f;
                }
            }
        }
    }
}

extern "C" void kernel_launch(void* const* d_in, const int* in_sizes, int n_in,
                              void* d_out, int out_size)
{
    const float* x   = (const float*)d_in[0];
    const float* w   = (const float*)d_in[1];
    const float* rng = (const float*)d_in[2];
    float* out = (float*)d_out;

    // (BATCH + OUT_F) warps = 8192 -> 1024 blocks of 8 warps; each block also
    // zero-fills 4096 float4 of the output.
    fsu_pack_zero_kernel<<<1024, 256>>>(x, w, rng,
                                        reinterpret_cast<float4*>(out));

    fsu_match_kernel<<<BATCH / MROWS, 1024>>>(out);  // 128 blocks
}